// round 1
// baseline (speedup 1.0000x reference)
#include <cuda_runtime.h>
#include <cstdint>
#include <math.h>

// ---------------------------------------------------------------------------
// NeuralODE Tsit5 (fixed 100 steps) — persistent-CTA fp32 kernel.
// Each CTA owns TM=32 batch rows and runs the whole time loop locally.
// GEMM inner loops use packed fma.rn.f32x2 (2 FMA/instr) with W tiles
// cp.async double-buffered into SMEM.
// ---------------------------------------------------------------------------

#define BATCH   4096
#define DIM     64
#define WIDTH   256
#define NTT     101
#define TM      32
#define NCTA    (BATCH / TM)      // 128
#define THREADS 256

#define ACT_STRIDE 260
#define ACT_SIZE   (TM * ACT_STRIDE)   // 8320 floats
#define WTILE      8192                // floats per W tile (32KB)
#define WBUF_SIZE  (2 * WTILE)
#define ZK_SIZE    (TM * DIM)          // 2048 floats

#define SMEM_FLOATS (2*ACT_SIZE + WBUF_SIZE + ZK_SIZE + ZK_SIZE + 6*ZK_SIZE)
#define SMEM_BYTES  (SMEM_FLOATS * 4)

// Tsit5 tableau (stage s uses row s, j < s entries)
__constant__ float c_A[6][5] = {
    {0.f, 0.f, 0.f, 0.f, 0.f},
    {0.161f, 0.f, 0.f, 0.f, 0.f},
    {-0.008480655492356989f, 0.335480655492357f, 0.f, 0.f, 0.f},
    {2.8971530571054935f, -6.359448489975075f, 4.3622954328695815f, 0.f, 0.f},
    {5.325864828439257f, -11.748883564062828f, 7.4955393428898365f, -0.09249506636175525f, 0.f},
    {5.86145544294642f, -12.92096931784711f, 8.159367898576159f, -0.071584973281401f, -0.028269050394068383f}
};
__constant__ float c_B[6] = {
    0.09646076681806523f, 0.01f, 0.4798896504144996f,
    1.379008574103742f, -3.290069515436081f, 2.324710524099774f
};

// ---- packed f32x2 helpers ----
__device__ __forceinline__ unsigned long long pk2(float lo, float hi) {
    unsigned long long r;
    asm("mov.b64 %0, {%1, %2};" : "=l"(r) : "f"(lo), "f"(hi));
    return r;
}
__device__ __forceinline__ void upk2(unsigned long long v, float &lo, float &hi) {
    asm("mov.b64 {%0, %1}, %2;" : "=f"(lo), "=f"(hi) : "l"(v));
}
__device__ __forceinline__ void ffma2(unsigned long long &d,
                                      unsigned long long a,
                                      unsigned long long b) {
    asm("fma.rn.f32x2 %0, %1, %2, %0;" : "+l"(d) : "l"(a), "l"(b));
}

// ---- cp.async helpers ----
__device__ __forceinline__ void cpa16(float *smem_dst, const float *gmem_src) {
    unsigned s = (unsigned)__cvta_generic_to_shared(smem_dst);
    asm volatile("cp.async.cg.shared.global [%0], [%1], 16;" :: "r"(s), "l"(gmem_src));
}
__device__ __forceinline__ void cpa_commit() {
    asm volatile("cp.async.commit_group;");
}
template <int N>
__device__ __forceinline__ void cpa_wait() {
    asm volatile("cp.async.wait_group %0;" :: "n"(N));
}

// ---------------------------------------------------------------------------
// One dense layer: O[TM][N] = act(A[TM][K] @ W[K][N] + b)
// W streamed from global (L2-resident) in KC-row tiles, double buffered.
// ---------------------------------------------------------------------------
template <int K, int N, bool ACT>
__device__ __forceinline__ void layer(const float *__restrict__ A, int ast,
                                      float *__restrict__ O, int ost,
                                      const float *__restrict__ Wg,
                                      const float *__restrict__ bg,
                                      float *__restrict__ wbuf) {
    constexpr int KC    = WTILE / N;          // 32 (N=256) or 128 (N=64)
    constexpr int TILES = K / KC;             // 2 or 8
    constexpr int CT    = (N >= 256) ? 4 : 2; // cols per thread
    constexpr int NCG   = N / CT;             // col groups
    constexpr int RT    = (TM * N) / (THREADS * CT); // rows per thread
    constexpr int NP    = CT / 2;             // packed col pairs

    const int tid = threadIdx.x;
    const int cg  = tid % NCG;
    const int rg  = tid / NCG;
    const int r0  = rg * RT;
    const int c0  = cg * CT;

    unsigned long long acc[RT][NP];
    {
        float bv[CT];
#pragma unroll
        for (int j = 0; j < CT; j++) bv[j] = __ldg(bg + c0 + j);
#pragma unroll
        for (int r = 0; r < RT; r++)
#pragma unroll
            for (int p = 0; p < NP; p++) acc[r][p] = pk2(bv[2*p], bv[2*p+1]);
    }

    // prefetch tile 0
    for (int i = tid; i < WTILE / 4; i += THREADS)
        cpa16(wbuf + i * 4, Wg + i * 4);
    cpa_commit();

    for (int tile = 0; tile < TILES; ++tile) {
        if (tile + 1 < TILES) {
            const float *src = Wg + (tile + 1) * WTILE;
            float *dst = wbuf + ((tile + 1) & 1) * WTILE;
            for (int i = tid; i < WTILE / 4; i += THREADS)
                cpa16(dst + i * 4, src + i * 4);
            cpa_commit();
            cpa_wait<1>();
        } else {
            cpa_wait<0>();
        }
        __syncthreads();

        const float *Wt = wbuf + (tile & 1) * WTILE;
        const float *arow[RT];
#pragma unroll
        for (int r = 0; r < RT; r++)
            arow[r] = A + (r0 + r) * ast + tile * KC;

#pragma unroll 8
        for (int k = 0; k < KC; k++) {
            unsigned long long wp[NP];
            if constexpr (CT == 4) {
                float4 w = *reinterpret_cast<const float4 *>(Wt + k * N + c0);
                wp[0] = pk2(w.x, w.y);
                wp[1] = pk2(w.z, w.w);
            } else {
                float2 w = *reinterpret_cast<const float2 *>(Wt + k * N + c0);
                wp[0] = pk2(w.x, w.y);
            }
#pragma unroll
            for (int r = 0; r < RT; r++) {
                float a = arow[r][k];
                unsigned long long ap = pk2(a, a);
#pragma unroll
                for (int p = 0; p < NP; p++) ffma2(acc[r][p], ap, wp[p]);
            }
        }
        __syncthreads();
    }

    // epilogue: optional tanh, write to O
#pragma unroll
    for (int r = 0; r < RT; r++) {
#pragma unroll
        for (int p = 0; p < NP; p++) {
            float x0, x1;
            upk2(acc[r][p], x0, x1);
            if (ACT) { x0 = tanhf(x0); x1 = tanhf(x1); }
            float2 v; v.x = x0; v.y = x1;
            *reinterpret_cast<float2 *>(O + (r0 + r) * ost + c0 + 2 * p) = v;
        }
    }
}

// ---------------------------------------------------------------------------
__global__ void __launch_bounds__(THREADS, 1)
node_kernel(const float *__restrict__ ts, const float *__restrict__ y0,
            const float *__restrict__ W0, const float *__restrict__ b0,
            const float *__restrict__ W1, const float *__restrict__ b1,
            const float *__restrict__ W2, const float *__restrict__ b2,
            const float *__restrict__ W3, const float *__restrict__ b3,
            float *__restrict__ out) {
    extern __shared__ float sm[];
    float *act0 = sm;
    float *act1 = act0 + ACT_SIZE;
    float *wbuf = act1 + ACT_SIZE;
    float *zbuf = wbuf + WBUF_SIZE;
    float *ybuf = zbuf + ZK_SIZE;
    float *kbuf = ybuf + ZK_SIZE;   // 6 * ZK_SIZE

    const int tid = threadIdx.x;
    const int cta = blockIdx.x;

    // load y0 slice into SMEM and emit out[0]
    {
        const float4 *src = reinterpret_cast<const float4 *>(y0 + (size_t)cta * TM * DIM);
        float4 *o0 = reinterpret_cast<float4 *>(out) + (size_t)cta * (TM * DIM / 4);
        float4 *yb = reinterpret_cast<float4 *>(ybuf);
        for (int i = tid; i < TM * DIM / 4; i += THREADS) {
            float4 v = src[i];
            yb[i] = v;
            o0[i] = v;
        }
    }
    __syncthreads();

    for (int t = 1; t < NTT; ++t) {
        const float h = __ldg(ts + t) - __ldg(ts + t - 1);

        for (int s = 0; s < 6; ++s) {
            // z = y + h * sum_{j<s} A[s][j] * k_j
            {
                float4 *zb = reinterpret_cast<float4 *>(zbuf);
                const float4 *yb = reinterpret_cast<const float4 *>(ybuf);
                for (int i = tid; i < TM * DIM / 4; i += THREADS) {
                    float4 v = yb[i];
                    for (int j = 0; j < s; j++) {
                        float c = h * c_A[s][j];
                        float4 kv = reinterpret_cast<const float4 *>(kbuf + j * ZK_SIZE)[i];
                        v.x += c * kv.x; v.y += c * kv.y;
                        v.z += c * kv.z; v.w += c * kv.w;
                    }
                    zb[i] = v;
                }
            }
            __syncthreads();

            layer<DIM,   WIDTH, true >(zbuf, DIM,        act0, ACT_STRIDE, W0, b0, wbuf);
            layer<WIDTH, WIDTH, true >(act0, ACT_STRIDE, act1, ACT_STRIDE, W1, b1, wbuf);
            layer<WIDTH, WIDTH, true >(act1, ACT_STRIDE, act0, ACT_STRIDE, W2, b2, wbuf);
            layer<WIDTH, DIM,   false>(act0, ACT_STRIDE, kbuf + s * ZK_SIZE, DIM, W3, b3, wbuf);
            __syncthreads();
        }

        // y += h * sum_j B[j] * k_j ; write out[t]
        {
            float4 *ob = reinterpret_cast<float4 *>(out) +
                         (size_t)t * (BATCH * DIM / 4) + (size_t)cta * (TM * DIM / 4);
            float4 *yb = reinterpret_cast<float4 *>(ybuf);
            for (int i = tid; i < TM * DIM / 4; i += THREADS) {
                float4 v = yb[i];
#pragma unroll
                for (int j = 0; j < 6; j++) {
                    float c = h * c_B[j];
                    float4 kv = reinterpret_cast<const float4 *>(kbuf + j * ZK_SIZE)[i];
                    v.x += c * kv.x; v.y += c * kv.y;
                    v.z += c * kv.z; v.w += c * kv.w;
                }
                yb[i] = v;
                ob[i] = v;
            }
        }
        __syncthreads();
    }
}

// ---------------------------------------------------------------------------
extern "C" void kernel_launch(void *const *d_in, const int *in_sizes, int n_in,
                              void *d_out, int out_size) {
    const float *ts = (const float *)d_in[0];
    const float *y0 = (const float *)d_in[1];
    const float *W0 = (const float *)d_in[2];
    const float *b0 = (const float *)d_in[3];
    const float *W1 = (const float *)d_in[4];
    const float *b1 = (const float *)d_in[5];
    const float *W2 = (const float *)d_in[6];
    const float *b2 = (const float *)d_in[7];
    const float *W3 = (const float *)d_in[8];
    const float *b3 = (const float *)d_in[9];
    float *out = (float *)d_out;

    cudaFuncSetAttribute(node_kernel,
                         cudaFuncAttributeMaxDynamicSharedMemorySize, SMEM_BYTES);
    node_kernel<<<NCTA, THREADS, SMEM_BYTES>>>(ts, y0, W0, b0, W1, b1,
                                               W2, b2, W3, b3, out);
}